// round 7
// baseline (speedup 1.0000x reference)
#include <cuda_runtime.h>
#include <math_constants.h>

// ChamferDistance: x1,x2 = [B=8, N=M=8192, 3] fp32.
// out = [ loss (1) | dist1 (B*N) | dist2 (B*M) ]
//
// R7: R6 (2 CTAs/SM, 8 warps/SMSP, single-barrier double-buffered tiles)
// + R4's rolling 1-jj register prefetch to hide LDS latency. To stay under
// the 64-reg cap, n1 (=|a|^2) is recomputed from global at flush time
// instead of living in registers through the mainloop.

constexpr int Bc = 8;
constexpr int Nc = 8192;
constexpr int Mc = 8192;
constexpr int THREADS = 512;
constexpr int PTS = 4;                        // A-points per thread (each dup'd)
constexpr int TILE_N = THREADS * PTS;         // 2048
constexpr int NCHUNKS = Nc / TILE_N;          // 4
constexpr int TILE_M = 256;                   // B-points per slice
constexpr int JP = TILE_M / 2;                // 128 j-pairs
constexpr int MSLICES = Mc / TILE_M;          // 32
constexpr int NACH = 2 * Bc * NCHUNKS;        // 64 A-chunks
constexpr int NTILES = NACH * MSLICES;        // 2048
constexpr int GRID = 296;                     // 2 CTAs per SM

__device__ __forceinline__ unsigned long long pk2(float lo, float hi) {
    unsigned long long r;
    asm("mov.b64 %0, {%1, %2};" : "=l"(r) : "f"(lo), "f"(hi));
    return r;
}
__device__ __forceinline__ unsigned long long ffma2(unsigned long long a,
                                                    unsigned long long b,
                                                    unsigned long long c) {
    unsigned long long d;
    asm("fma.rn.f32x2 %0, %1, %2, %3;" : "=l"(d) : "l"(a), "l"(b), "l"(c));
    return d;
}
__device__ __forceinline__ void upk2(unsigned long long v, float& lo, float& hi) {
    asm("mov.b64 {%0, %1}, %2;" : "=f"(lo), "=f"(hi) : "l"(v));
}

// decode tile id -> (dir, b, nbase, ms)
__device__ __forceinline__ void decode_tile(int t, int& dir, int& b, int& nbase, int& ms) {
    const int ach = t >> 5;          // [0,64)
    ms = t & (MSLICES - 1);
    const int db = ach >> 2;         // dir*8 + b
    dir = db >> 3;
    b = db & 7;
    nbase = (ach & 3) * TILE_N;
}

__device__ __forceinline__ void flush_chunk(int dir, int b, int nbase, int tid,
                                            const float* __restrict__ x1,
                                            const float* __restrict__ x2,
                                            float* __restrict__ dist1,
                                            float* __restrict__ dist2,
                                            const float* eminE, const float* eminO)
{
    const float* __restrict__ P = dir ? x2 : x1;
    float* __restrict__ outd = dir ? dist2 : dist1;
#pragma unroll
    for (int k = 0; k < PTS; k++) {
        const int n = nbase + k * THREADS + tid;
        const float* p = P + ((size_t)b * Nc + n) * 3;
        const float ax = p[0], ay = p[1], az = p[2];
        const float n1 = fmaf(ax, ax, fmaf(ay, ay, az * az));
        const float e = fminf(eminE[k], eminO[k]);
        const float d = fmaxf(n1 + e, 0.0f);
        atomicMin((int*)&outd[(size_t)b * Nc + n], __float_as_int(d));
    }
}

__global__ void __launch_bounds__(THREADS, 2)
chamfer_pass_kernel(const float* __restrict__ x1, const float* __restrict__ x2,
                    float* __restrict__ dist1, float* __restrict__ dist2)
{
    // 2 buffers; per j-pair: {bx2_e,bx2_o, by2_e,by2_o, bz2_e,bz2_o, n2_e,n2_o}
    __shared__ __align__(16) float tile[2][JP * 8];

    const int tid = threadIdx.x;
    const int bid = blockIdx.x;
    const int tstart = (bid * NTILES) / GRID;
    const int tend   = ((bid + 1) * NTILES) / GRID;

    unsigned long long axp[PTS], ayp[PTS], azp[PTS];
    float eminE[PTS], eminO[PTS];
    int cur_ach = -1;
    int cur_dir = 0, cur_b = 0, cur_nbase = 0;

    // prologue: fill buffer 0 with tile tstart
    {
        int dir, b, nbase, ms;
        decode_tile(tstart, dir, b, nbase, ms);
        const float* __restrict__ Q = dir ? x1 : x2;
        if (tid < JP) {
            const float* q = Q + ((size_t)b * Mc + ms * TILE_M + 2 * tid) * 3;
            const float bxe = q[0], bye = q[1], bze = q[2];
            const float bxo = q[3], byo = q[4], bzo = q[5];
            const float n2e = fmaf(bxe, bxe, fmaf(bye, bye, bze * bze));
            const float n2o = fmaf(bxo, bxo, fmaf(byo, byo, bzo * bzo));
            float4* s = reinterpret_cast<float4*>(&tile[0][tid * 8]);
            s[0] = make_float4(-2.0f * bxe, -2.0f * bxo, -2.0f * bye, -2.0f * byo);
            s[1] = make_float4(-2.0f * bze, -2.0f * bzo, n2e, n2o);
        }
    }

    for (int t = tstart; t < tend; t++) {
        const int buf = (t - tstart) & 1;

        // single barrier per round: orders this round's fill (done last round)
        // before compute, and last round's compute before we refill its buffer.
        __syncthreads();

        // fill NEXT tile into the other buffer
        if (t + 1 < tend && tid < JP) {
            int ndir, nb, nnbase, nms;
            decode_tile(t + 1, ndir, nb, nnbase, nms);
            const float* __restrict__ Q = ndir ? x1 : x2;
            const float* q = Q + ((size_t)nb * Mc + nms * TILE_M + 2 * tid) * 3;
            const float bxe = q[0], bye = q[1], bze = q[2];
            const float bxo = q[3], byo = q[4], bzo = q[5];
            const float n2e = fmaf(bxe, bxe, fmaf(bye, bye, bze * bze));
            const float n2o = fmaf(bxo, bxo, fmaf(byo, byo, bzo * bzo));
            float4* s = reinterpret_cast<float4*>(&tile[buf ^ 1][tid * 8]);
            s[0] = make_float4(-2.0f * bxe, -2.0f * bxo, -2.0f * bye, -2.0f * byo);
            s[1] = make_float4(-2.0f * bze, -2.0f * bzo, n2e, n2o);
        }

        // A-chunk management for CURRENT tile
        const int ach = t >> 5;
        if (ach != cur_ach) {
            if (cur_ach >= 0)
                flush_chunk(cur_dir, cur_b, cur_nbase, tid, x1, x2, dist1, dist2,
                            eminE, eminO);
            cur_ach = ach;
            int ms_un;
            decode_tile(t, cur_dir, cur_b, cur_nbase, ms_un);
            const float* __restrict__ P = cur_dir ? x2 : x1;
#pragma unroll
            for (int k = 0; k < PTS; k++) {
                const int n = cur_nbase + k * THREADS + tid;
                const float* p = P + ((size_t)cur_b * Nc + n) * 3;
                const float ax = p[0], ay = p[1], az = p[2];
                axp[k] = pk2(ax, ax);
                ayp[k] = pk2(ay, ay);
                azp[k] = pk2(az, az);
                eminE[k] = CUDART_INF_F;
                eminO[k] = CUDART_INF_F;
            }
        }

        // compute CURRENT buffer with rolling 1-jj register prefetch
        const ulonglong2* sp = reinterpret_cast<const ulonglong2*>(tile[buf]);
        ulonglong2 c0 = sp[0];
        ulonglong2 c1 = sp[1];
#pragma unroll 4
        for (int jj = 0; jj < JP; jj++) {
            ulonglong2 n0, n1v;
            if (jj + 1 < JP) {
                n0 = sp[2 * (jj + 1)];
                n1v = sp[2 * (jj + 1) + 1];
            }
            // c0.x={bx2_e,bx2_o}  c0.y={by2_e,by2_o}  c1.x={bz2_e,bz2_o}  c1.y={n2_e,n2_o}
#pragma unroll
            for (int k = 0; k < PTS; k++) {
                unsigned long long e = ffma2(axp[k], c0.x, c1.y);
                e = ffma2(ayp[k], c0.y, e);
                e = ffma2(azp[k], c1.x, e);
                float flo, fhi;
                upk2(e, flo, fhi);
                eminE[k] = fminf(eminE[k], flo);
                eminO[k] = fminf(eminO[k], fhi);
            }
            c0 = n0;
            c1 = n1v;
        }
    }

    if (cur_ach >= 0)
        flush_chunk(cur_dir, cur_b, cur_nbase, tid, x1, x2, dist1, dist2,
                    eminE, eminO);
}

// ---- deterministic 2-stage loss reduction ----
__device__ float g_partials[128];

__global__ void __launch_bounds__(256)
sum_stage1(const float* __restrict__ dists)   // dists = out+1, length 2*B*N
{
    __shared__ float red[256];
    const int tid = threadIdx.x;
    const int base = blockIdx.x * 1024;
    float s = 0.0f;
#pragma unroll
    for (int i = 0; i < 4; i++) s += dists[base + i * 256 + tid];
    red[tid] = s;
    __syncthreads();
    for (int w = 128; w > 0; w >>= 1) {
        if (tid < w) red[tid] += red[tid + w];
        __syncthreads();
    }
    if (tid == 0) g_partials[blockIdx.x] = red[0];
}

__global__ void __launch_bounds__(128)
sum_stage2(float* __restrict__ out)
{
    __shared__ float red[128];
    const int tid = threadIdx.x;
    red[tid] = g_partials[tid];
    __syncthreads();
    for (int w = 64; w > 0; w >>= 1) {
        if (tid < w) red[tid] += red[tid + w];
        __syncthreads();
    }
    if (tid == 0) out[0] = red[0] * (1.0f / (float)(Bc * Nc));
}

extern "C" void kernel_launch(void* const* d_in, const int* in_sizes, int n_in,
                              void* d_out, int out_size)
{
    const float* x1 = (const float*)d_in[0];
    const float* x2 = (const float*)d_in[1];
    float* out = (float*)d_out;
    float* dist1 = out + 1;
    float* dist2 = out + 1 + Bc * Nc;

    // Sentinel-fill dist arrays: 0x7F7F7F7F = 3.39e38 > any real sq-distance.
    cudaMemsetAsync(out + 1, 0x7F, (size_t)2 * Bc * Nc * sizeof(float));

    chamfer_pass_kernel<<<GRID, THREADS>>>(x1, x2, dist1, dist2);

    sum_stage1<<<128, 256>>>(out + 1);
    sum_stage2<<<1, 128>>>(out);
}